// round 2
// baseline (speedup 1.0000x reference)
#include <cuda_runtime.h>

// Fused curve-LUT apply (trilinear grid_sample over 8x256x256 control grid + tanh).
//   out[b,c,h,w] = tanh( sum_i trilin( param[b, c*24+i*8+z, yc, xc], ix(w), iy(h), iz(x[b,i,h,w]) ) )
//
// R2 layout: CTA = 128x8 pixel tile, 8 warps (1 warp per row), each thread owns
// 4 consecutive x-pixels. Within a warp the control-point x-cell is distinct
// (and ~consecutive) per lane, so with an ODD point stride (27 floats) the
// scalar LDS bank index = 27*p + 3*z0 + c is a near-permutation of lanes ->
// ~conflict-free shared reads (R1 measured ~2.4-way conflicts with 9-way
// shared p). Depth padded to 9 levels (z=8 duplicates z=7) so the z1 corner
// reads are base+3 immediates, no min().

#define TW 128
#define TH 8
#define XS 34          // control x-cells covered by a 128-px tile (+clamp pad)
#define YS 4           // control y-cells covered by an 8-px tile
#define NP (XS * YS)   // 136 points
#define PSTR 27        // floats per (i, point): 9 z-levels * 3 channels (odd!)
#define NTHREADS 256

__device__ __forceinline__ float fast_tanh(float v) {
    float y;
    asm("tanh.approx.f32 %0, %1;" : "=f"(y) : "f"(v));
    return y;
}

__global__ __launch_bounds__(NTHREADS)
void curve_apply_kernel(const float* __restrict__ x,
                        const float* __restrict__ param,
                        float* __restrict__ out)
{
    __shared__ float sh[3 * NP * PSTR];   // 11016 floats = 44.1 KB

    const int b  = blockIdx.z;
    const int w0 = blockIdx.x * TW;
    const int h0 = blockIdx.y * TH;
    const float r = 255.0f / 1023.0f;
    const int xbase = (int)floorf((float)w0 * r);
    const int ybase = (int)floorf((float)h0 * r);
    const int tid = threadIdx.x;

    // ---- Stage control patch: param[b, plane, y, x] -> sh[i][p][z*3+c] ----
    const float* prm = param + (size_t)b * 72 * 65536;
    #pragma unroll 1
    for (int idx = tid; idx < 72 * NP; idx += NTHREADS) {
        int plane = idx / NP;
        int pos   = idx - plane * NP;      // consecutive dx -> coalesced LDG
        int dy = pos / XS;
        int dx = pos - dy * XS;
        int yy = min(ybase + dy, 255);
        int xx = min(xbase + dx, 255);
        float v = __ldg(prm + plane * 65536 + yy * 256 + xx);
        int c  = plane / 24;
        int rm = plane - c * 24;
        int i  = rm >> 3;
        int z  = rm & 7;
        float* dst = sh + (i * NP + pos) * PSTR + z * 3 + c;
        dst[0] = v;
        if (z == 7) dst[3] = v;            // pad level z=8 = clamp(z=7)
    }
    __syncthreads();

    // ---- Pixel loop: warp = one row, lane = 4 consecutive x-pixels ----
    const int lane = tid & 31;
    const int row  = tid >> 5;
    const int h = h0 + row;

    float iyf = fminf((float)h * r, 255.0f);
    float y0f = floorf(iyf);
    float wy  = iyf - y0f;
    int   y0  = (int)y0f;
    int   dy0 = y0 - ybase;
    int   dy1 = min(y0 + 1, 255) - ybase;

    const int wpx = w0 + lane * 4;
    const int pix = h * 1024 + wpx;

    const float* xb = x   + (size_t)b * 3 * 1048576;
    float*       ob = out + (size_t)b * 3 * 1048576;

    const float4 xv0 = __ldg((const float4*)(xb + pix));
    const float4 xv1 = __ldg((const float4*)(xb + 1048576 + pix));
    const float4 xv2 = __ldg((const float4*)(xb + 2097152 + pix));

    float4 r0, r1, r2;

    #pragma unroll
    for (int j = 0; j < 4; j++) {
        const int w = wpx + j;
        float ixf = fminf((float)w * r, 255.0f);
        float x0f = floorf(ixf);
        float wx  = ixf - x0f;
        int   x0  = (int)x0f;
        int   dx0 = x0 - xbase;
        int   dx1 = min(x0 + 1, 255) - xbase;

        int p00 = (dy0 * XS + dx0) * PSTR;
        int p01 = (dy0 * XS + dx1) * PSTR;
        int p10 = (dy1 * XS + dx0) * PSTR;
        int p11 = (dy1 * XS + dx1) * PSTR;

        float w11 = wy * wx;
        float w10 = wy - w11;
        float w01 = wx - w11;
        float w00 = 1.0f - wy - wx + w11;

        float acc0 = 0.f, acc1 = 0.f, acc2 = 0.f;

        #pragma unroll
        for (int i = 0; i < 3; i++) {
            float gz = (i == 0) ? ((j == 0) ? xv0.x : (j == 1) ? xv0.y : (j == 2) ? xv0.z : xv0.w)
                     : (i == 1) ? ((j == 0) ? xv1.x : (j == 1) ? xv1.y : (j == 2) ? xv1.z : xv1.w)
                                : ((j == 0) ? xv2.x : (j == 1) ? xv2.y : (j == 2) ? xv2.z : xv2.w);
            float izf = fminf(fmaxf(fmaf(gz, 3.5f, 3.5f), 0.0f), 7.0f);
            float z0f = floorf(izf);
            float wz  = izf - z0f;
            int   o0  = (int)z0f * 3;
            const float* shi = sh + i * (NP * PSTR) + o0;

            #define CORNER(PB, WC)                                           \
            {                                                                \
                const float* p = shi + (PB);                                 \
                float a0 = p[0], a1 = p[1], a2 = p[2];                       \
                float b0 = p[3], b1 = p[4], b2 = p[5];                       \
                acc0 = fmaf((WC), fmaf(wz, b0 - a0, a0), acc0);              \
                acc1 = fmaf((WC), fmaf(wz, b1 - a1, a1), acc1);              \
                acc2 = fmaf((WC), fmaf(wz, b2 - a2, a2), acc2);              \
            }
            CORNER(p00, w00)
            CORNER(p01, w01)
            CORNER(p10, w10)
            CORNER(p11, w11)
            #undef CORNER
        }

        float t0 = fast_tanh(acc0);
        float t1 = fast_tanh(acc1);
        float t2 = fast_tanh(acc2);
        if (j == 0)      { r0.x = t0; r1.x = t1; r2.x = t2; }
        else if (j == 1) { r0.y = t0; r1.y = t1; r2.y = t2; }
        else if (j == 2) { r0.z = t0; r1.z = t1; r2.z = t2; }
        else             { r0.w = t0; r1.w = t1; r2.w = t2; }
    }

    *(float4*)(ob + pix)           = r0;
    *(float4*)(ob + 1048576 + pix) = r1;
    *(float4*)(ob + 2097152 + pix) = r2;
}

extern "C" void kernel_launch(void* const* d_in, const int* in_sizes, int n_in,
                              void* d_out, int out_size)
{
    const float* x     = (const float*)d_in[0];   // [4,3,1024,1024] fp32
    const float* param = (const float*)d_in[1];   // [4,72,256,256]  fp32
    float*       out   = (float*)d_out;           // [4,3,1024,1024] fp32

    dim3 grid(1024 / TW, 1024 / TH, 4);
    curve_apply_kernel<<<grid, NTHREADS>>>(x, param, out);
}

// round 3
// speedup vs baseline: 1.1437x; 1.1437x over previous
#include <cuda_runtime.h>

// Fused curve-LUT apply (trilinear grid_sample over 8x256x256 control grid + tanh).
//
// R3: back to R1's 1-pixel-per-lane structure (which measured best), but the
// shared layout stores each (point, channel) depth column as 8 OVERLAPPING
// float2 pairs pair[k] = (v[k], v[min(k+1,7)]).  A z-lerp then needs ONE
// LDS.64 per (corner, channel) instead of two LDS.32:
//   36 LDS.64/pixel vs 72 LDS.32/pixel  -> half the shared-pipe issue slots
// and far fewer address IADDs (ALU pipe was at 46%).
// Layout: sh[i][point][c*8 + k] of float2, point stride 29 float2 (odd in the
// 16 double-bank space).  Tile 32x16 px -> 60 points -> 41.8 KB static smem,
// 5 CTAs/SM, 100% theoretical occupancy.

#define TW 32
#define TH 16
#define XS 10
#define YS 6
#define NP (XS * YS)        // 60 points
#define PSTR 29             // float2 per point (24 used: 3 ch * 8 pairs)
#define ISTR (NP * PSTR)    // float2 per curve set i
#define NTHREADS 256

__device__ __forceinline__ float fast_tanh(float v) {
    float y;
    asm("tanh.approx.f32 %0, %1;" : "=f"(y) : "f"(v));
    return y;
}

__global__ __launch_bounds__(NTHREADS)
void curve_apply_kernel(const float* __restrict__ x,
                        const float* __restrict__ param,
                        float* __restrict__ out)
{
    __shared__ float2 sh[3 * ISTR];   // 5220 float2 = 41760 B

    const int b  = blockIdx.z;
    const int w0 = blockIdx.x * TW;
    const int h0 = blockIdx.y * TH;
    const float r = 255.0f / 1023.0f;
    const int xbase = (int)floorf((float)w0 * r);
    const int ybase = (int)floorf((float)h0 * r);
    const int tid = threadIdx.x;

    // ---- Stage control patch: param[b, plane, y, x] -> overlapping pairs ----
    // plane = c*24 + i*8 + z.  Value v[z] lands in pair[z].x and pair[z-1].y;
    // v[7] also fills pair[7].y (depth clamp).
    const float* prm = param + (size_t)b * 72 * 65536;
    #pragma unroll 1
    for (int idx = tid; idx < 72 * NP; idx += NTHREADS) {
        int plane = idx / NP;
        int pos   = idx - plane * NP;
        int dy = pos / XS;
        int dx = pos - dy * XS;
        int yy = min(ybase + dy, 255);
        int xx = min(xbase + dx, 255);
        float v = __ldg(prm + plane * 65536 + yy * 256 + xx);
        int c  = plane / 24;
        int rm = plane - c * 24;
        int i  = rm >> 3;
        int z  = rm & 7;
        float* base = (float*)(sh + (i * NP + pos) * PSTR + c * 8);
        base[2 * z] = v;                 // pair[z].x
        if (z > 0)  base[2 * z - 1] = v; // pair[z-1].y
        if (z == 7) base[15] = v;        // pair[7].y  (clamp)
    }
    __syncthreads();

    // ---- Pixel loop: lane = consecutive x, warp-row covers 2 image rows ----
    const int lane = tid & 31;
    const int row  = tid >> 5;
    const int w = w0 + lane;

    float ixf = fminf((float)w * r, 255.0f);
    float x0f = floorf(ixf);
    float wx  = ixf - x0f;
    int   x0  = (int)x0f;
    int   dx0 = x0 - xbase;
    int   dx1 = min(x0 + 1, 255) - xbase;

    const float* xb = x   + (size_t)b * 3 * 1048576;
    float*       ob = out + (size_t)b * 3 * 1048576;

    #pragma unroll
    for (int k = 0; k < 2; k++) {
        int h = h0 + row + 8 * k;
        float iyf = fminf((float)h * r, 255.0f);
        float y0f = floorf(iyf);
        float wy  = iyf - y0f;
        int   y0  = (int)y0f;
        int   dy0 = y0 - ybase;
        int   dy1 = min(y0 + 1, 255) - ybase;

        int b00 = (dy0 * XS + dx0) * PSTR;
        int b01 = (dy0 * XS + dx1) * PSTR;
        int b10 = (dy1 * XS + dx0) * PSTR;
        int b11 = (dy1 * XS + dx1) * PSTR;

        float w11 = wy * wx;
        float w10 = wy - w11;
        float w01 = wx - w11;
        float w00 = 1.0f - wy - wx + w11;

        int pix = h * 1024 + w;
        float acc0 = 0.f, acc1 = 0.f, acc2 = 0.f;

        #pragma unroll
        for (int i = 0; i < 3; i++) {
            float gz  = __ldg(xb + (size_t)i * 1048576 + pix);
            float izf = fminf(fmaxf(fmaf(gz, 3.5f, 3.5f), 0.0f), 7.0f);
            float z0f = floorf(izf);
            float wz  = izf - z0f;
            const float2* s0 = sh + i * ISTR + (int)z0f;

            #define CORNER(PB, WC)                                           \
            {                                                                \
                const float2* p = s0 + (PB);                                 \
                float2 q0 = p[0];                                            \
                float2 q1 = p[8];                                            \
                float2 q2 = p[16];                                           \
                acc0 = fmaf((WC), fmaf(wz, q0.y - q0.x, q0.x), acc0);        \
                acc1 = fmaf((WC), fmaf(wz, q1.y - q1.x, q1.x), acc1);        \
                acc2 = fmaf((WC), fmaf(wz, q2.y - q2.x, q2.x), acc2);        \
            }
            CORNER(b00, w00)
            CORNER(b01, w01)
            CORNER(b10, w10)
            CORNER(b11, w11)
            #undef CORNER
        }

        ob[pix]               = fast_tanh(acc0);
        ob[1048576 + pix]     = fast_tanh(acc1);
        ob[2097152 + pix]     = fast_tanh(acc2);
    }
}

extern "C" void kernel_launch(void* const* d_in, const int* in_sizes, int n_in,
                              void* d_out, int out_size)
{
    const float* x     = (const float*)d_in[0];   // [4,3,1024,1024] fp32
    const float* param = (const float*)d_in[1];   // [4,72,256,256]  fp32
    float*       out   = (float*)d_out;           // [4,3,1024,1024] fp32

    dim3 grid(1024 / TW, 1024 / TH, 4);
    curve_apply_kernel<<<grid, NTHREADS>>>(x, param, out);
}

// round 4
// speedup vs baseline: 1.4665x; 1.2822x over previous
#include <cuda_runtime.h>
#include <cuda_fp16.h>

// Fused curve-LUT apply (trilinear grid_sample over 8x256x256 control grid + tanh).
//
// R4 = R1 structure (32x32 tile, 1 px/lane, 4 rows/thread, 30KB smem) with the
// shared patch stored as FP16 OVERLAPPING PAIRS: pair[z] = (v[z], v[z+1]).
// One LDS.32 per (corner, channel) gives both z-lerp endpoints:
//   36 LDS.32 + 144 B/pixel  vs R1's  72 LDS.32 + 288 B/pixel.
// L1 wavefronts (the measured limiter) halve; smem stays 30KB so occupancy
// is unchanged. All arithmetic (weights, lerp, accumulation) stays fp32; only
// storage is fp16 (~1e-4 output rel-err, threshold 1e-3).

#define TW 32
#define TH 32
#define XS 10
#define YS 10
#define NP (XS * YS)       // 100 points
#define PSTR 25            // half2 per point (24 used: 3ch * 8 pairs), odd stride
#define ISTR (NP * PSTR)   // half2 per curve set
#define NTHREADS 256

__device__ __forceinline__ float fast_tanh(float v) {
    float y;
    asm("tanh.approx.f32 %0, %1;" : "=f"(y) : "f"(v));
    return y;
}

__global__ __launch_bounds__(NTHREADS)
void curve_apply_kernel(const float* __restrict__ x,
                        const float* __restrict__ param,
                        float* __restrict__ out)
{
    __shared__ __half2 sh[3 * ISTR];   // 7500 half2 = 30,000 B

    const int b  = blockIdx.z;
    const int w0 = blockIdx.x * TW;
    const int h0 = blockIdx.y * TH;
    const float r = 255.0f / 1023.0f;
    const int xbase = (int)floorf((float)w0 * r);
    const int ybase = (int)floorf((float)h0 * r);
    const int tid = threadIdx.x;

    // ---- Stage control patch -> fp16 overlapping pairs ----
    // plane = c*24 + i*8 + z.  v[z] -> pair[z].x and pair[z-1].y; z==7 also pair[7].y.
    const float* prm = param + (size_t)b * 72 * 65536;
    #pragma unroll 1
    for (int idx = tid; idx < 72 * NP; idx += NTHREADS) {
        int plane = idx / NP;
        int pos   = idx - plane * NP;
        int dy = pos / XS;
        int dx = pos - dy * XS;
        int yy = min(ybase + dy, 255);
        int xx = min(xbase + dx, 255);
        float v = __ldg(prm + plane * 65536 + yy * 256 + xx);
        int c  = plane / 24;
        int rm = plane - c * 24;
        int i  = rm >> 3;
        int z  = rm & 7;
        __half hv = __float2half_rn(v);
        __half* hb = (__half*)(sh + (i * NP + pos) * PSTR) + c * 16;
        hb[2 * z] = hv;                  // pair[z].x
        if (z > 0)  hb[2 * z - 1] = hv;  // pair[z-1].y
        if (z == 7) hb[15] = hv;         // pair[7].y (depth clamp)
    }
    __syncthreads();

    // ---- Pixel loop ----
    const int lane = tid & 31;
    const int rowi = tid >> 5;
    const int w = w0 + lane;

    float ixf = fminf((float)w * r, 255.0f);
    float x0f = floorf(ixf);
    float wx  = ixf - x0f;
    int   x0  = (int)x0f;
    int   dx0 = x0 - xbase;
    int   dx1 = min(x0 + 1, 255) - xbase;

    const float* xb = x   + (size_t)b * 3 * 1048576;
    float*       ob = out + (size_t)b * 3 * 1048576;

    #pragma unroll
    for (int k = 0; k < 4; k++) {
        int h = h0 + rowi + 8 * k;
        float iyf = fminf((float)h * r, 255.0f);
        float y0f = floorf(iyf);
        float wy  = iyf - y0f;
        int   y0  = (int)y0f;
        int   dy0 = y0 - ybase;
        int   dy1 = min(y0 + 1, 255) - ybase;

        int cb00 = (dy0 * XS + dx0) * PSTR;
        int cb01 = (dy0 * XS + dx1) * PSTR;
        int cb10 = (dy1 * XS + dx0) * PSTR;
        int cb11 = (dy1 * XS + dx1) * PSTR;

        float w11 = wy * wx;
        float w10 = wy - w11;
        float w01 = wx - w11;
        float w00 = 1.0f - wy - wx + w11;

        int pix = h * 1024 + w;
        float acc0 = 0.f, acc1 = 0.f, acc2 = 0.f;

        #pragma unroll
        for (int i = 0; i < 3; i++) {
            float gz  = __ldg(xb + (size_t)i * 1048576 + pix);
            float izf = fminf(fmaxf(fmaf(gz, 3.5f, 3.5f), 0.0f), 7.0f);
            float z0f = floorf(izf);
            float wz  = izf - z0f;
            int   z0  = (int)z0f;
            const __half2* shi = sh + i * ISTR + z0;

            // Accumulate (a, b) endpoints over the 4 corners in fp32,
            // single z-lerp per channel at the end.
            float A0 = 0.f, B0 = 0.f, A1 = 0.f, B1 = 0.f, A2 = 0.f, B2 = 0.f;

            #define CORNER(CB, WC)                                           \
            {                                                                \
                const __half2* p = shi + (CB);                               \
                float2 q0 = __half22float2(p[0]);                            \
                float2 q1 = __half22float2(p[8]);                            \
                float2 q2 = __half22float2(p[16]);                           \
                A0 = fmaf((WC), q0.x, A0);  B0 = fmaf((WC), q0.y, B0);       \
                A1 = fmaf((WC), q1.x, A1);  B1 = fmaf((WC), q1.y, B1);       \
                A2 = fmaf((WC), q2.x, A2);  B2 = fmaf((WC), q2.y, B2);       \
            }
            CORNER(cb00, w00)
            CORNER(cb01, w01)
            CORNER(cb10, w10)
            CORNER(cb11, w11)
            #undef CORNER

            acc0 += fmaf(wz, B0 - A0, A0);
            acc1 += fmaf(wz, B1 - A1, A1);
            acc2 += fmaf(wz, B2 - A2, A2);
        }

        ob[pix]           = fast_tanh(acc0);
        ob[1048576 + pix] = fast_tanh(acc1);
        ob[2097152 + pix] = fast_tanh(acc2);
    }
}

extern "C" void kernel_launch(void* const* d_in, const int* in_sizes, int n_in,
                              void* d_out, int out_size)
{
    const float* x     = (const float*)d_in[0];   // [4,3,1024,1024] fp32
    const float* param = (const float*)d_in[1];   // [4,72,256,256]  fp32
    float*       out   = (float*)d_out;           // [4,3,1024,1024] fp32

    dim3 grid(1024 / TW, 1024 / TH, 4);
    curve_apply_kernel<<<grid, NTHREADS>>>(x, param, out);
}